// round 4
// baseline (speedup 1.0000x reference)
#include <cuda_runtime.h>
#include <math.h>

// ---- problem constants ----
#define NL    12
#define DMODEL 1152
#define NHD   4
#define HDIM  256
#define FDIM  6912
#define VOC   32768
#define TT    128
#define CCTX  1920
#define SS    2048          // CCTX + TT
#define QKVW  1536          // (NH + 2) * HD
#define CAPV  50.0f
#define SCL   0.0625f       // 1/sqrt(256)

// ---- device scratch (static, no allocation) ----
__device__ __align__(256) float g_h[TT * DMODEL];
__device__ __align__(256) float g_x[TT * DMODEL];
__device__ __align__(256) float g_qkv[TT * QKVW];
__device__ __align__(256) float g_q[NHD * TT * HDIM];
__device__ __align__(256) float g_kfull[SS * HDIM];
__device__ __align__(256) float g_vfull[HDIM * SS];
__device__ __align__(256) float g_scores[NHD * TT * SS];
__device__ __align__(256) float g_attno[TT * NHD * HDIM];
__device__ __align__(256) float g_proj[TT * DMODEL];
__device__ __align__(256) float g_ffa[TT * FDIM];
__device__ __align__(256) float g_ffb[TT * FDIM];
__device__ __align__(256) float g_part[4 * 1024 * 1024];

// ============================================================
// block reductions
// ============================================================
__device__ __forceinline__ float blockReduceSum(float v) {
    __shared__ float sh[33];
    __syncthreads();
    int lane = threadIdx.x & 31, wid = threadIdx.x >> 5;
    #pragma unroll
    for (int o = 16; o; o >>= 1) v += __shfl_xor_sync(0xffffffffu, v, o);
    if (lane == 0) sh[wid] = v;
    __syncthreads();
    int nw = (blockDim.x + 31) >> 5;
    v = (threadIdx.x < nw) ? sh[threadIdx.x] : 0.f;
    if (wid == 0) {
        #pragma unroll
        for (int o = 16; o; o >>= 1) v += __shfl_xor_sync(0xffffffffu, v, o);
        if (lane == 0) sh[32] = v;
    }
    __syncthreads();
    return sh[32];
}

__device__ __forceinline__ float blockReduceMax(float v) {
    __shared__ float sh[33];
    __syncthreads();
    int lane = threadIdx.x & 31, wid = threadIdx.x >> 5;
    #pragma unroll
    for (int o = 16; o; o >>= 1) v = fmaxf(v, __shfl_xor_sync(0xffffffffu, v, o));
    if (lane == 0) sh[wid] = v;
    __syncthreads();
    int nw = (blockDim.x + 31) >> 5;
    v = (threadIdx.x < nw) ? sh[threadIdx.x] : -3.4e38f;
    if (wid == 0) {
        #pragma unroll
        for (int o = 16; o; o >>= 1) v = fmaxf(v, __shfl_xor_sync(0xffffffffu, v, o));
        if (lane == 0) sh[32] = v;
    }
    __syncthreads();
    return sh[32];
}

// ============================================================
// SGEMM: C[M=128, N] = A[128, K] * op(B), fp32.
// BT=false: B row-major (K x N).  BT=true: B row-major (N x K) -> A*B^T.
// Deterministic split-K: each (split) writes partials; reduce kernel sums.
// ============================================================
template <bool BT>
__global__ __launch_bounds__(256) void sgemm_kernel(
    const float* __restrict__ Aall, int lda, long sAb,
    const float* __restrict__ Ball, int ldb, long sBb,
    float* __restrict__ Cdir, int ldc, long sCb,
    float* __restrict__ Cpart,
    int N, int K, int splits)
{
    const int nb = blockIdx.x;        // N tile
    const int split = blockIdx.y;
    const int batch = blockIdx.z;
    const int Kc = K / splits;

    const float* A = Aall + (long)batch * sAb + (long)split * Kc;
    const float* B;
    if (BT) B = Ball + (long)batch * sBb + (long)(nb * 128) * ldb + (long)split * Kc;
    else    B = Ball + (long)batch * sBb + (long)((long)split * Kc) * ldb + nb * 128;

    __shared__ float As[16][128];
    __shared__ float Bs[16][128];

    const int tid = threadIdx.x;
    const int tx = tid & 15;          // n dir
    const int ty = tid >> 4;          // m dir
    const int mA = tid >> 1;          // 0..127
    const int hA = tid & 1;           // which 8-chunk of 16

    float acc[8][8];
    #pragma unroll
    for (int i = 0; i < 8; i++)
        #pragma unroll
        for (int j = 0; j < 8; j++) acc[i][j] = 0.f;

    for (int k0 = 0; k0 < Kc; k0 += 16) {
        // load A tile transposed: As[k][m]
        {
            const float* ap = A + (long)mA * lda + k0 + hA * 8;
            float4 v0 = *(const float4*)ap;
            float4 v1 = *(const float4*)(ap + 4);
            int kb = hA * 8;
            As[kb + 0][mA] = v0.x; As[kb + 1][mA] = v0.y;
            As[kb + 2][mA] = v0.z; As[kb + 3][mA] = v0.w;
            As[kb + 4][mA] = v1.x; As[kb + 5][mA] = v1.y;
            As[kb + 6][mA] = v1.z; As[kb + 7][mA] = v1.w;
        }
        // load B tile: Bs[k][n]
        if (BT) {
            const float* bp = B + (long)mA * ldb + k0 + hA * 8;
            float4 v0 = *(const float4*)bp;
            float4 v1 = *(const float4*)(bp + 4);
            int kb = hA * 8;
            Bs[kb + 0][mA] = v0.x; Bs[kb + 1][mA] = v0.y;
            Bs[kb + 2][mA] = v0.z; Bs[kb + 3][mA] = v0.w;
            Bs[kb + 4][mA] = v1.x; Bs[kb + 5][mA] = v1.y;
            Bs[kb + 6][mA] = v1.z; Bs[kb + 7][mA] = v1.w;
        } else {
            int kr = tid >> 4;
            int nc = (tid & 15) * 8;
            const float* bp = B + (long)(k0 + kr) * ldb + nc;
            float4 v0 = *(const float4*)bp;
            float4 v1 = *(const float4*)(bp + 4);
            Bs[kr][nc + 0] = v0.x; Bs[kr][nc + 1] = v0.y;
            Bs[kr][nc + 2] = v0.z; Bs[kr][nc + 3] = v0.w;
            Bs[kr][nc + 4] = v1.x; Bs[kr][nc + 5] = v1.y;
            Bs[kr][nc + 6] = v1.z; Bs[kr][nc + 7] = v1.w;
        }
        __syncthreads();

        #pragma unroll
        for (int kk = 0; kk < 16; kk++) {
            float a[8], b[8];
            *(float4*)(a)     = *(const float4*)&As[kk][ty * 8];
            *(float4*)(a + 4) = *(const float4*)&As[kk][ty * 8 + 4];
            *(float4*)(b)     = *(const float4*)&Bs[kk][tx * 8];
            *(float4*)(b + 4) = *(const float4*)&Bs[kk][tx * 8 + 4];
            #pragma unroll
            for (int i = 0; i < 8; i++)
                #pragma unroll
                for (int j = 0; j < 8; j++)
                    acc[i][j] = fmaf(a[i], b[j], acc[i][j]);
        }
        __syncthreads();
    }

    if (splits == 1) {
        float* Cb = Cdir + (long)batch * sCb;
        #pragma unroll
        for (int i = 0; i < 8; i++) {
            float* cr = Cb + (long)(ty * 8 + i) * ldc + nb * 128 + tx * 8;
            #pragma unroll
            for (int j = 0; j < 8; j++) cr[j] = acc[i][j];
        }
    } else {
        float* P = Cpart + (long)(batch * splits + split) * 128 * N;
        #pragma unroll
        for (int i = 0; i < 8; i++) {
            float* pr = P + (long)(ty * 8 + i) * N + nb * 128 + tx * 8;
            #pragma unroll
            for (int j = 0; j < 8; j++) pr[j] = acc[i][j];
        }
    }
}

__global__ void reduce_kernel(const float* __restrict__ part,
                              float* __restrict__ C, int ldc, long sCb,
                              int N, int splits, long total)
{
    long idx = (long)blockIdx.x * blockDim.x + threadIdx.x;
    if (idx >= total) return;
    int n = (int)(idx % N);
    long r = idx / N;
    int m = (int)(r % 128);
    int b = (int)(r / 128);
    float s = 0.f;
    for (int sp = 0; sp < splits; sp++)
        s += part[((long)(b * splits + sp) * 128 + m) * N + n];
    C[(long)b * sCb + (long)m * ldc + n] = s;
}

// ============================================================
// elementwise / norm kernels
// ============================================================
__global__ void copy_kernel(const float* __restrict__ src, float* __restrict__ dst, int n) {
    int i = blockIdx.x * blockDim.x + threadIdx.x;
    if (i < n) dst[i] = src[i];
}

__global__ void copyk_kernel(const float* __restrict__ src) {  // (C,HD) contiguous
    int i = blockIdx.x * blockDim.x + threadIdx.x;
    if (i < CCTX * HDIM) g_kfull[i] = src[i];
}

__global__ void copyv_kernel(const float* __restrict__ src) {  // (HD,C) -> rows of (HD,S)
    int i = blockIdx.x * blockDim.x + threadIdx.x;
    if (i < HDIM * CCTX) {
        int d = i / CCTX, c = i % CCTX;
        g_vfull[(long)d * SS + c] = src[i];
    }
}

// y[t,:] = rms(x[t,:]) * (1+w)
__global__ void rmsnorm_kernel(const float* __restrict__ x, const float* __restrict__ w,
                               float* __restrict__ y) {
    int t = blockIdx.x;
    const float* xr = x + (long)t * DMODEL;
    float s = 0.f;
    for (int d = threadIdx.x; d < DMODEL; d += blockDim.x) { float v = xr[d]; s += v * v; }
    s = blockReduceSum(s);
    float rs = rsqrtf(s / DMODEL + 1e-6f);
    float* yr = y + (long)t * DMODEL;
    for (int d = threadIdx.x; d < DMODEL; d += blockDim.x)
        yr[d] = xr[d] * rs * (1.f + w[d]);
}

// h[t,:] += rms(p[t,:]) * (1+w)
__global__ void addrms_kernel(const float* __restrict__ p, const float* __restrict__ w) {
    int t = blockIdx.x;
    const float* pr = p + (long)t * DMODEL;
    float s = 0.f;
    for (int d = threadIdx.x; d < DMODEL; d += blockDim.x) { float v = pr[d]; s += v * v; }
    s = blockReduceSum(s);
    float rs = rsqrtf(s / DMODEL + 1e-6f);
    float* hr = g_h + (long)t * DMODEL;
    for (int d = threadIdx.x; d < DMODEL; d += blockDim.x)
        hr[d] += pr[d] * rs * (1.f + w[d]);
}

// Per (t, j): j<4 q-head (rms+rope -> g_q), j=4 k (rms+rope -> g_kfull, kout),
// j=5 v (-> g_vfull col, vout). 256 threads = HD.
__global__ void qkvpost_kernel(const float* __restrict__ qn_w, const float* __restrict__ kn_w,
                               const float* __restrict__ pcos, const float* __restrict__ psin,
                               float* __restrict__ kout, float* __restrict__ vout) {
    int t = blockIdx.x, j = blockIdx.y, d = threadIdx.x;
    float v = g_qkv[(long)t * QKVW + j * HDIM + d];
    if (j == 5) {
        g_vfull[(long)d * SS + CCTX + t] = v;
        vout[(long)d * TT + t] = v;
        return;
    }
    float s = blockReduceSum(v * v);
    float rs = rsqrtf(s / HDIM + 1e-6f);
    const float* wn = (j == 4) ? kn_w : qn_w;
    float n = v * rs * (1.f + wn[d]);
    __shared__ float sn[HDIM];
    sn[d] = n;
    __syncthreads();
    float rot = (d < HDIM / 2) ? -sn[d + HDIM / 2] : sn[d - HDIM / 2];
    float r = n * pcos[(long)t * HDIM + d] + rot * psin[(long)t * HDIM + d];
    if (j == 4) {
        g_kfull[(long)(CCTX + t) * HDIM + d] = r;
        kout[(long)t * HDIM + d] = r;
    } else {
        g_q[((long)j * TT + t) * HDIM + d] = r;
    }
}

// tanh-cap + mask + softmax, in place on g_scores. grid (T, NH), 256 threads x 8.
__global__ void softmax_kernel(const float* __restrict__ mask) {
    int t = blockIdx.x, h = blockIdx.y;
    float* row = g_scores + ((long)h * TT + t) * SS;
    const float* mrow = mask + (long)t * SS;
    const float f = SCL / CAPV;
    float vloc[8];
    float mx = -3.4e38f;
    #pragma unroll
    for (int i = 0; i < 8; i++) {
        int s = threadIdx.x + i * 256;
        float val = tanhf(row[s] * f) * CAPV + mrow[s];
        vloc[i] = val;
        mx = fmaxf(mx, val);
    }
    mx = blockReduceMax(mx);
    float sum = 0.f;
    #pragma unroll
    for (int i = 0; i < 8; i++) { float e = expf(vloc[i] - mx); vloc[i] = e; sum += e; }
    sum = blockReduceSum(sum);
    float inv = 1.f / sum;
    #pragma unroll
    for (int i = 0; i < 8; i++) row[threadIdx.x + i * 256] = vloc[i] * inv;
}

__global__ void gelumul_kernel() {
    int i = blockIdx.x * blockDim.x + threadIdx.x;
    if (i < TT * FDIM) {
        float x = g_ffa[i], u = g_ffb[i];
        float g = 0.5f * x * (1.f + tanhf(0.7978845608028654f * (x + 0.044715f * x * x * x)));
        g_ffa[i] = g * u;
    }
}

// ============================================================
// host orchestration
// ============================================================
static void run_gemm(const float* A, int lda, long sAb,
                     const float* B, int ldb, long sBb,
                     float* C, int ldc, long sCb,
                     int N, int K, int splits, int batches, bool bT, float* part)
{
    dim3 grid(N / 128, splits, batches);
    if (bT)
        sgemm_kernel<true><<<grid, 256>>>(A, lda, sAb, B, ldb, sBb,
                                          C, ldc, sCb, part, N, K, splits);
    else
        sgemm_kernel<false><<<grid, 256>>>(A, lda, sAb, B, ldb, sBb,
                                           C, ldc, sCb, part, N, K, splits);
    if (splits > 1) {
        long total = (long)batches * 128 * N;
        int blocks = (int)((total + 255) / 256);
        reduce_kernel<<<blocks, 256>>>(part, C, ldc, sCb, N, splits, total);
    }
}

extern "C" void kernel_launch(void* const* d_in, const int* in_sizes, int n_in,
                              void* d_out, int out_size)
{
    const float* embeddings   = (const float*)d_in[0];
    const float* mask_global  = (const float*)d_in[1];
    const float* mask_local   = (const float*)d_in[2];
    const float* pe_cos       = (const float*)d_in[3];
    const float* pe_sin       = (const float*)d_in[4];
    const float* pe_cos_loc   = (const float*)d_in[5];
    const float* pe_sin_loc   = (const float*)d_in[6];
    const float* kv_k         = (const float*)d_in[7];
    const float* kv_v         = (const float*)d_in[8];
    const float* pre_attn_w   = (const float*)d_in[9];
    const float* q_norm_w     = (const float*)d_in[10];
    const float* k_norm_w     = (const float*)d_in[11];
    const float* post_attn_w  = (const float*)d_in[12];
    const float* pre_ff_w     = (const float*)d_in[13];
    const float* post_ff_w    = (const float*)d_in[14];
    const float* final_w      = (const float*)d_in[15];
    const float* w_qkv        = (const float*)d_in[16];
    const float* w_out        = (const float*)d_in[17];
    const float* w_gate       = (const float*)d_in[18];
    const float* w_up         = (const float*)d_in[19];
    const float* w_down       = (const float*)d_in[20];
    const float* w_lm         = (const float*)d_in[21];

    float* out = (float*)d_out;
    float* out_logits = out;                               // (T, V)
    float* out_k = out + (long)TT * VOC;                   // (L, T, HD)
    float* out_v = out_k + (long)NL * TT * HDIM;           // (L, HD, T)

    float *ph, *px, *pqkv, *pq, *pkf, *pvf, *psc, *pao, *ppr, *pfa, *pfb, *ppart;
    cudaGetSymbolAddress((void**)&ph, g_h);
    cudaGetSymbolAddress((void**)&px, g_x);
    cudaGetSymbolAddress((void**)&pqkv, g_qkv);
    cudaGetSymbolAddress((void**)&pq, g_q);
    cudaGetSymbolAddress((void**)&pkf, g_kfull);
    cudaGetSymbolAddress((void**)&pvf, g_vfull);
    cudaGetSymbolAddress((void**)&psc, g_scores);
    cudaGetSymbolAddress((void**)&pao, g_attno);
    cudaGetSymbolAddress((void**)&ppr, g_proj);
    cudaGetSymbolAddress((void**)&pfa, g_ffa);
    cudaGetSymbolAddress((void**)&pfb, g_ffb);
    cudaGetSymbolAddress((void**)&ppart, g_part);

    // h = embeddings
    copy_kernel<<<(TT * DMODEL + 255) / 256, 256>>>(embeddings, ph, TT * DMODEL);

    for (int i = 0; i < NL; i++) {
        bool is_local = ((i + 1) % 6) == 0;
        const float* pcos = is_local ? pe_cos_loc : pe_cos;
        const float* psin = is_local ? pe_sin_loc : pe_sin;
        const float* mask = is_local ? mask_local : mask_global;

        // x = rms(h, pre_attn_w[i])
        rmsnorm_kernel<<<TT, 256>>>(ph, pre_attn_w + (long)i * DMODEL, px);

        // qkv = x @ w_qkv[i]   (128 x 1152 x 1536)
        run_gemm(px, DMODEL, 0, w_qkv + (long)i * DMODEL * QKVW, QKVW, 0,
                 pqkv, QKVW, 0, QKVW, DMODEL, 8, 1, false, ppart);

        // KV cache copies into full buffers
        copyk_kernel<<<(CCTX * HDIM + 255) / 256, 256>>>(kv_k + (long)i * CCTX * HDIM);
        copyv_kernel<<<(HDIM * CCTX + 255) / 256, 256>>>(kv_v + (long)i * HDIM * CCTX);

        // q/k rms+rope, v transpose; also writes output k/v slices
        qkvpost_kernel<<<dim3(TT, 6), HDIM>>>(q_norm_w + (long)i * HDIM,
                                              k_norm_w + (long)i * HDIM,
                                              pcos, psin,
                                              out_k + (long)i * TT * HDIM,
                                              out_v + (long)i * HDIM * TT);

        // scores[h] = q_h (128x256) @ k_full^T (2048x256)^T
        run_gemm(pq, HDIM, (long)TT * HDIM, pkf, HDIM, 0,
                 psc, SS, (long)TT * SS, SS, HDIM, 2, NHD, true, ppart);

        // tanh-cap + mask + softmax
        softmax_kernel<<<dim3(TT, NHD), 256>>>(mask);

        // out[h] = attn_h (128x2048) @ v_full^T (256x2048)^T  -> (T, NH*HD) interleaved
        run_gemm(psc, SS, (long)TT * SS, pvf, SS, 0,
                 pao, NHD * HDIM, (long)HDIM, HDIM, SS, 16, NHD, true, ppart);

        // proj = attno (128x1024) @ w_out[i] (1024x1152)
        run_gemm(pao, NHD * HDIM, 0, w_out + (long)i * NHD * HDIM * DMODEL, DMODEL, 0,
                 ppr, DMODEL, 0, DMODEL, NHD * HDIM, 16, 1, false, ppart);

        // h += rms(proj, post_attn_w[i])
        addrms_kernel<<<TT, 256>>>(ppr, post_attn_w + (long)i * DMODEL);

        // fx = rms(h, pre_ff_w[i])
        rmsnorm_kernel<<<TT, 256>>>(ph, pre_ff_w + (long)i * DMODEL, px);

        // gate / up (128 x 1152 x 6912 each)
        run_gemm(px, DMODEL, 0, w_gate + (long)i * DMODEL * FDIM, FDIM, 0,
                 pfa, FDIM, 0, FDIM, DMODEL, 4, 1, false, ppart);
        run_gemm(px, DMODEL, 0, w_up + (long)i * DMODEL * FDIM, FDIM, 0,
                 pfb, FDIM, 0, FDIM, DMODEL, 4, 1, false, ppart);

        gelumul_kernel<<<(TT * FDIM + 255) / 256, 256>>>();

        // down (128 x 6912 x 1152)
        run_gemm(pfa, FDIM, 0, w_down + (long)i * FDIM * DMODEL, DMODEL, 0,
                 ppr, DMODEL, 0, DMODEL, FDIM, 16, 1, false, ppart);

        // h += rms(ff, post_ff_w[i])
        addrms_kernel<<<TT, 256>>>(ppr, post_ff_w + (long)i * DMODEL);
    }

    // logits = rms(h, final_w) @ w_lm  (128 x 1152 x 32768), direct to d_out
    rmsnorm_kernel<<<TT, 256>>>(ph, final_w, px);
    run_gemm(px, DMODEL, 0, w_lm, VOC, 0,
             out_logits, VOC, 0, VOC, DMODEL, 1, 1, false, ppart);
}

// round 8
// speedup vs baseline: 1.9477x; 1.9477x over previous
#include <cuda_runtime.h>
#include <cuda_bf16.h>
#include <math.h>
#include <stdint.h>

#define NL 12
#define DMODEL 1152
#define NHD 4
#define HDIM 256
#define FDIM 6912
#define VOC 32768
#define TT 128
#define CCTX 1920
#define SS 2048
#define QKVW 1536
#define CAPV 50.0f
#define SCL 0.0625f

__device__ __align__(256) float g_h[TT * DMODEL];
__device__ __align__(256) float g_x[TT * DMODEL];
__device__ __align__(256) float g_qkv[TT * QKVW];
__device__ __align__(256) float g_q[NHD * TT * HDIM];
__device__ __align__(256) float g_kfull[SS * HDIM];
__device__ __align__(256) float g_vfull[HDIM * SS];
__device__ __align__(256) float g_scores[NHD * TT * SS];
__device__ __align__(256) float g_attno[TT * NHD * HDIM];
__device__ __align__(256) float g_proj[TT * DMODEL];
__device__ __align__(256) float g_ffa[TT * FDIM];
__device__ __align__(256) float g_ffb[TT * FDIM];
__device__ __align__(256) float g_part[4 * 1024 * 1024];

// ============================================================
// bf16x3 mma.sync GEMM. C[128, N] = A[128,K] * op(B), fp32 in/out.
// TRANS=false: B gmem [N,K] (K contig). TRANS=true: B gmem [K,N] (N contig).
// K chunk = 32 orig. SMEM tile per buf: [128 rows][64 bf16] = 16KB
// (ext cols 0-31 = hi, 32-63 = lo). Double buffered A+B = 64KB.
// ============================================================
#define SMEM_GEMM_BYTES 65536

__device__ __forceinline__ uint32_t smem_u32(const void* p) {
    uint32_t a;
    asm("{ .reg .u64 t; cvta.to.shared.u64 t, %1; cvt.u32.u64 %0, t; }" : "=r"(a) : "l"(p));
    return a;
}
__device__ __forceinline__ uint32_t sw128(uint32_t o) { return o ^ ((o >> 3) & 0x70u); }

__device__ __forceinline__ uint32_t packbf2(float a, float b) {
    __nv_bfloat162 t = __floats2bfloat162_rn(a, b);
    return *(uint32_t*)&t;
}
__device__ __forceinline__ void hilo(float v, float& h, float& l) {
    __nv_bfloat16 hb = __float2bfloat16_rn(v);
    h = __bfloat162float(hb);
    l = v - h;
}
__device__ __forceinline__ void ldm4(uint32_t* r, uint32_t a) {
    asm volatile("ldmatrix.sync.aligned.m8n8.x4.shared.b16 {%0,%1,%2,%3}, [%4];"
                 : "=r"(r[0]), "=r"(r[1]), "=r"(r[2]), "=r"(r[3]) : "r"(a));
}
__device__ __forceinline__ void mma16816(float* c, const uint32_t* a, uint32_t b0, uint32_t b1) {
    asm volatile(
        "mma.sync.aligned.m16n8k16.row.col.f32.bf16.bf16.f32 "
        "{%0,%1,%2,%3}, {%4,%5,%6,%7}, {%8,%9}, {%0,%1,%2,%3};"
        : "+f"(c[0]), "+f"(c[1]), "+f"(c[2]), "+f"(c[3])
        : "r"(a[0]), "r"(a[1]), "r"(a[2]), "r"(a[3]), "r"(b0), "r"(b1));
}
__device__ __forceinline__ void st8(uint32_t a, uint32_t v0, uint32_t v1) {
    asm volatile("st.shared.v2.b32 [%0], {%1,%2};" :: "r"(a), "r"(v0), "r"(v1) : "memory");
}

// store 4 consecutive-k fp32 as hi/lo bf16 into swizzled tile
__device__ __forceinline__ void store4(uint32_t base, uint32_t ob, float4 v) {
    float h0, l0, h1, l1, h2, l2, h3, l3;
    hilo(v.x, h0, l0); hilo(v.y, h1, l1); hilo(v.z, h2, l2); hilo(v.w, h3, l3);
    st8(base + sw128(ob),      packbf2(h0, h1), packbf2(h2, h3));
    st8(base + sw128(ob + 64), packbf2(l0, l1), packbf2(l2, l3));
}

template <bool TRANS>
__global__ void __launch_bounds__(256, 1) mmagemm(
    const float* __restrict__ Aall, int lda, long sAb,
    const float* __restrict__ Ball, int ldb, long sBb,
    float* __restrict__ Call, int ldc, long sCb,
    float* __restrict__ Cpart, int N, int K, int splits)
{
    extern __shared__ char smraw[];
    const uint32_t sb = smem_u32(smraw);
    const int tid = threadIdx.x;
    const int lane = tid & 31, w = tid >> 5;
    const int wm = w & 1, wn = w >> 1;
    const int nb = blockIdx.x, split = blockIdx.y, batch = blockIdx.z;
    const int Kc = K / splits;
    const int NC = Kc >> 5;

    const float* A = Aall + (long)batch * sAb + (long)split * Kc;
    const float* B = Ball + (long)batch * sBb;
    if (TRANS) B += (long)((long)split * Kc) * ldb + nb * 128;
    else       B += (long)(nb * 128) * ldb + split * Kc;

    float c[4][4][4];
    #pragma unroll
    for (int a = 0; a < 4; a++)
        #pragma unroll
        for (int b = 0; b < 4; b++)
            #pragma unroll
            for (int r = 0; r < 4; r++) c[a][b][r] = 0.f;

    const int arow = tid >> 1, ahalf = tid & 1;     // A / non-trans-B load mapping
    const int bn = tid & 127, bkg = tid >> 7;       // TRANS B load mapping

    float4 ra[4];
    float4 rb4[4];
    float rbs[16];

    // ---- load helpers (chunk index i) ----
    auto loadA = [&](int i) {
        const float* ap = A + (long)arow * lda + i * 32 + ahalf * 16;
        #pragma unroll
        for (int q = 0; q < 4; q++) ra[q] = ((const float4*)ap)[q];
    };
    auto loadB = [&](int i) {
        if (TRANS) {
            const float* bp = B + ((long)i * 32 + bkg * 16) * ldb + bn;
            #pragma unroll
            for (int q = 0; q < 16; q++) rbs[q] = bp[(long)q * ldb];
        } else {
            const float* bp = B + (long)arow * ldb + i * 32 + ahalf * 16;
            #pragma unroll
            for (int q = 0; q < 4; q++) rb4[q] = ((const float4*)bp)[q];
        }
    };
    auto storeA = [&](int p) {
        const uint32_t base = sb + p * 16384;
        #pragma unroll
        for (int q = 0; q < 4; q++)
            store4(base, arow * 128 + ahalf * 32 + q * 8, ra[q]);
    };
    auto storeB = [&](int p) {
        const uint32_t base = sb + 32768 + p * 16384;
        if (TRANS) {
            #pragma unroll
            for (int g = 0; g < 4; g++) {
                float4 v = make_float4(rbs[g * 4], rbs[g * 4 + 1], rbs[g * 4 + 2], rbs[g * 4 + 3]);
                store4(base, bn * 128 + bkg * 32 + g * 8, v);
            }
        } else {
            #pragma unroll
            for (int q = 0; q < 4; q++)
                store4(base, arow * 128 + ahalf * 32 + q * 8, rb4[q]);
        }
    };

    const int m0 = wm * 64, n0 = wn * 32;
    const uint32_t lrow = lane & 15;
    const uint32_t lsel = (lane >> 4) * 16;

    auto mmachunk = [&](int p) {
        const uint32_t ab = sb + p * 16384;
        const uint32_t bb = sb + 32768 + p * 16384;
        #pragma unroll
        for (int j = 0; j < 2; j++) {
            const uint32_t cb = j * 32;
            uint32_t ahi[4][4], alo[4][4], bhi[2][4], blo[2][4];
            #pragma unroll
            for (int mt = 0; mt < 4; mt++) {
                uint32_t o = (m0 + mt * 16 + lrow) * 128 + cb + lsel;
                ldm4(ahi[mt], ab + sw128(o));
                ldm4(alo[mt], ab + sw128(o + 64));
            }
            #pragma unroll
            for (int pp = 0; pp < 2; pp++) {
                uint32_t o = (n0 + pp * 16 + lrow) * 128 + cb + lsel;
                ldm4(bhi[pp], bb + sw128(o));
                ldm4(blo[pp], bb + sw128(o + 64));
            }
            #pragma unroll
            for (int mt = 0; mt < 4; mt++)
                #pragma unroll
                for (int nt = 0; nt < 4; nt++) {
                    int pp = nt >> 1, qq = nt & 1;
                    mma16816(c[mt][nt], ahi[mt], bhi[pp][qq], bhi[pp][qq + 2]);
                    mma16816(c[mt][nt], alo[mt], bhi[pp][qq], bhi[pp][qq + 2]);
                    mma16816(c[mt][nt], ahi[mt], blo[pp][qq], blo[pp][qq + 2]);
                }
        }
    };

    // ---- pipeline ----
    loadA(0); loadB(0);
    storeA(0); storeB(0);
    __syncthreads();
    for (int i = 0; i < NC; i++) {
        const int p = i & 1;
        if (i + 1 < NC) { loadA(i + 1); loadB(i + 1); }
        mmachunk(p);
        __syncthreads();
        if (i + 1 < NC) {
            storeA(p ^ 1); storeB(p ^ 1);
            __syncthreads();
        }
    }

    // ---- epilogue ----
    float* Cb;
    long ldx;
    if (splits == 1) { Cb = Call + (long)batch * sCb + nb * 128; ldx = ldc; }
    else { Cb = Cpart + ((long)(batch * splits + split) * 128) * N + nb * 128; ldx = N; }
    #pragma unroll
    for (int mt = 0; mt < 4; mt++)
        #pragma unroll
        for (int nt = 0; nt < 4; nt++) {
            int r0 = m0 + mt * 16 + (lane >> 2);
            int c0 = n0 + nt * 8 + (lane & 3) * 2;
            float2 v0 = make_float2(c[mt][nt][0], c[mt][nt][1]);
            float2 v1 = make_float2(c[mt][nt][2], c[mt][nt][3]);
            *(float2*)&Cb[(long)r0 * ldx + c0] = v0;
            *(float2*)&Cb[(long)(r0 + 8) * ldx + c0] = v1;
        }
}

__global__ void reduce_kernel(const float* __restrict__ part, float* __restrict__ C,
                              int ldc, long sCb, int N, int splits, long total)
{
    long idx = (long)blockIdx.x * blockDim.x + threadIdx.x;
    if (idx >= total) return;
    int n = (int)(idx % N);
    long r = idx / N;
    int m = (int)(r % 128);
    int b = (int)(r / 128);
    float s = 0.f;
    for (int sp = 0; sp < splits; sp++)
        s += part[((long)(b * splits + sp) * 128 + m) * N + n];
    C[(long)b * sCb + (long)m * ldc + n] = s;
}

// ---------- reductions ----------
__device__ __forceinline__ float blockReduceSum(float v) {
    __shared__ float sh[33];
    __syncthreads();
    int lane = threadIdx.x & 31, wid = threadIdx.x >> 5;
    #pragma unroll
    for (int o = 16; o; o >>= 1) v += __shfl_xor_sync(0xffffffffu, v, o);
    if (lane == 0) sh[wid] = v;
    __syncthreads();
    int nw = (blockDim.x + 31) >> 5;
    v = (threadIdx.x < nw) ? sh[threadIdx.x] : 0.f;
    if (wid == 0) {
        #pragma unroll
        for (int o = 16; o; o >>= 1) v += __shfl_xor_sync(0xffffffffu, v, o);
        if (lane == 0) sh[32] = v;
    }
    __syncthreads();
    return sh[32];
}
__device__ __forceinline__ float blockReduceMax(float v) {
    __shared__ float sh[33];
    __syncthreads();
    int lane = threadIdx.x & 31, wid = threadIdx.x >> 5;
    #pragma unroll
    for (int o = 16; o; o >>= 1) v = fmaxf(v, __shfl_xor_sync(0xffffffffu, v, o));
    if (lane == 0) sh[wid] = v;
    __syncthreads();
    int nw = (blockDim.x + 31) >> 5;
    v = (threadIdx.x < nw) ? sh[threadIdx.x] : -3.4e38f;
    if (wid == 0) {
        #pragma unroll
        for (int o = 16; o; o >>= 1) v = fmaxf(v, __shfl_xor_sync(0xffffffffu, v, o));
        if (lane == 0) sh[32] = v;
    }
    __syncthreads();
    return sh[32];
}

// ---------- elementwise ----------
__global__ void copy_kernel(const float* __restrict__ s, float* __restrict__ d, int n) {
    int i = blockIdx.x * blockDim.x + threadIdx.x;
    if (i < n) d[i] = s[i];
}
__global__ void copyk_kernel(const float* __restrict__ src) {
    int i = blockIdx.x * blockDim.x + threadIdx.x;
    if (i < CCTX * HDIM) g_kfull[i] = src[i];
}
__global__ void copyv_kernel(const float* __restrict__ src) {
    int i = blockIdx.x * blockDim.x + threadIdx.x;
    if (i < HDIM * CCTX) {
        int d = i / CCTX, c = i % CCTX;
        g_vfull[(long)d * SS + c] = src[i];
    }
}
__global__ void rmsnorm_kernel(const float* __restrict__ x, const float* __restrict__ w,
                               float* __restrict__ y) {
    int t = blockIdx.x;
    const float* xr = x + (long)t * DMODEL;
    float s = 0.f;
    for (int d = threadIdx.x; d < DMODEL; d += blockDim.x) { float v = xr[d]; s += v * v; }
    s = blockReduceSum(s);
    float rs = rsqrtf(s / DMODEL + 1e-6f);
    float* yr = y + (long)t * DMODEL;
    for (int d = threadIdx.x; d < DMODEL; d += blockDim.x)
        yr[d] = xr[d] * rs * (1.f + w[d]);
}
__global__ void addrms_kernel(const float* __restrict__ p, const float* __restrict__ w) {
    int t = blockIdx.x;
    const float* pr = p + (long)t * DMODEL;
    float s = 0.f;
    for (int d = threadIdx.x; d < DMODEL; d += blockDim.x) { float v = pr[d]; s += v * v; }
    s = blockReduceSum(s);
    float rs = rsqrtf(s / DMODEL + 1e-6f);
    float* hr = g_h + (long)t * DMODEL;
    for (int d = threadIdx.x; d < DMODEL; d += blockDim.x)
        hr[d] += pr[d] * rs * (1.f + w[d]);
}
__global__ void qkvpost_kernel(const float* __restrict__ qn_w, const float* __restrict__ kn_w,
                               const float* __restrict__ pcos, const float* __restrict__ psin,
                               float* __restrict__ kout, float* __restrict__ vout) {
    int t = blockIdx.x, j = blockIdx.y, d = threadIdx.x;
    float v = g_qkv[(long)t * QKVW + j * HDIM + d];
    if (j == 5) {
        g_vfull[(long)d * SS + CCTX + t] = v;
        vout[(long)d * TT + t] = v;
        return;
    }
    float s = blockReduceSum(v * v);
    float rs = rsqrtf(s / HDIM + 1e-6f);
    const float* wn = (j == 4) ? kn_w : qn_w;
    float n = v * rs * (1.f + wn[d]);
    __shared__ float sn[HDIM];
    sn[d] = n;
    __syncthreads();
    float rot = (d < HDIM / 2) ? -sn[d + HDIM / 2] : sn[d - HDIM / 2];
    float r = n * pcos[(long)t * HDIM + d] + rot * psin[(long)t * HDIM + d];
    if (j == 4) {
        g_kfull[(long)(CCTX + t) * HDIM + d] = r;
        kout[(long)t * HDIM + d] = r;
    } else {
        g_q[((long)j * TT + t) * HDIM + d] = r;
    }
}
__global__ void softmax_kernel(const float* __restrict__ mask) {
    int t = blockIdx.x, h = blockIdx.y;
    float* row = g_scores + ((long)h * TT + t) * SS;
    const float* mrow = mask + (long)t * SS;
    const float f = SCL / CAPV;
    float vloc[8];
    float mx = -3.4e38f;
    #pragma unroll
    for (int i = 0; i < 8; i++) {
        int s = threadIdx.x + i * 256;
        float val = tanhf(row[s] * f) * CAPV + mrow[s];
        vloc[i] = val;
        mx = fmaxf(mx, val);
    }
    mx = blockReduceMax(mx);
    float sum = 0.f;
    #pragma unroll
    for (int i = 0; i < 8; i++) { float e = expf(vloc[i] - mx); vloc[i] = e; sum += e; }
    sum = blockReduceSum(sum);
    float inv = 1.f / sum;
    #pragma unroll
    for (int i = 0; i < 8; i++) row[threadIdx.x + i * 256] = vloc[i] * inv;
}
__global__ void gelumul_kernel() {
    int i = blockIdx.x * blockDim.x + threadIdx.x;
    if (i < TT * FDIM) {
        float x = g_ffa[i], u = g_ffb[i];
        float g = 0.5f * x * (1.f + tanhf(0.7978845608028654f * (x + 0.044715f * x * x * x)));
        g_ffa[i] = g * u;
    }
}

// ---------- host ----------
static void run_mma(const float* A, int lda, long sAb,
                    const float* B, int ldb, long sBb, bool trans,
                    float* C, int ldc, long sCb, float* part,
                    int N, int K, int splits, int batches)
{
    dim3 grid(N / 128, splits, batches);
    if (trans)
        mmagemm<true><<<grid, 256, SMEM_GEMM_BYTES>>>(A, lda, sAb, B, ldb, sBb,
                                                      C, ldc, sCb, part, N, K, splits);
    else
        mmagemm<false><<<grid, 256, SMEM_GEMM_BYTES>>>(A, lda, sAb, B, ldb, sBb,
                                                       C, ldc, sCb, part, N, K, splits);
    if (splits > 1) {
        long total = (long)batches * 128 * N;
        reduce_kernel<<<(int)((total + 255) / 256), 256>>>(part, C, ldc, sCb, N, splits, total);
    }
}

extern "C" void kernel_launch(void* const* d_in, const int* in_sizes, int n_in,
                              void* d_out, int out_size)
{
    const float* embeddings  = (const float*)d_in[0];
    const float* mask_global = (const float*)d_in[1];
    const float* mask_local  = (const float*)d_in[2];
    const float* pe_cos      = (const float*)d_in[3];
    const float* pe_sin      = (const float*)d_in[4];
    const float* pe_cos_loc  = (const float*)d_in[5];
    const float* pe_sin_loc  = (const float*)d_in[6];
    const float* kv_k        = (const float*)d_in[7];
    const float* kv_v        = (const float*)d_in[8];
    const float* pre_attn_w  = (const float*)d_in[9];
    const float* q_norm_w    = (const float*)d_in[10];
    const float* k_norm_w    = (const float*)d_in[11];
    const float* post_attn_w = (const float*)d_in[12];
    const float* pre_ff_w    = (const float*)d_in[13];
    const float* post_ff_w   = (const float*)d_in[14];
    const float* final_w     = (const float*)d_in[15];
    const float* w_qkv       = (const float*)d_in[16];
    const float* w_out       = (const float*)d_in[17];
    const float* w_gate      = (const float*)d_in[18];
    const float* w_up        = (const float*)d_in[19];
    const float* w_down      = (const float*)d_in[20];
    const float* w_lm        = (const float*)d_in[21];

    cudaFuncSetAttribute(mmagemm<false>, cudaFuncAttributeMaxDynamicSharedMemorySize, SMEM_GEMM_BYTES);
    cudaFuncSetAttribute(mmagemm<true>,  cudaFuncAttributeMaxDynamicSharedMemorySize, SMEM_GEMM_BYTES);

    float* out = (float*)d_out;
    float* out_logits = out;
    float* out_k = out + (long)TT * VOC;
    float* out_v = out_k + (long)NL * TT * HDIM;

    float *ph, *px, *pqkv, *pq, *pkf, *pvf, *psc, *pao, *ppr, *pfa, *pfb, *ppart;
    cudaGetSymbolAddress((void**)&ph, g_h);
    cudaGetSymbolAddress((void**)&px, g_x);
    cudaGetSymbolAddress((void**)&pqkv, g_qkv);
    cudaGetSymbolAddress((void**)&pq, g_q);
    cudaGetSymbolAddress((void**)&pkf, g_kfull);
    cudaGetSymbolAddress((void**)&pvf, g_vfull);
    cudaGetSymbolAddress((void**)&psc, g_scores);
    cudaGetSymbolAddress((void**)&pao, g_attno);
    cudaGetSymbolAddress((void**)&ppr, g_proj);
    cudaGetSymbolAddress((void**)&pfa, g_ffa);
    cudaGetSymbolAddress((void**)&pfb, g_ffb);
    cudaGetSymbolAddress((void**)&ppart, g_part);

    copy_kernel<<<(TT * DMODEL + 255) / 256, 256>>>(embeddings, ph, TT * DMODEL);

    for (int i = 0; i < NL; i++) {
        bool is_local = ((i + 1) % 6) == 0;
        const float* pcos = is_local ? pe_cos_loc : pe_cos;
        const float* psin = is_local ? pe_sin_loc : pe_sin;
        const float* mask = is_local ? mask_local : mask_global;

        rmsnorm_kernel<<<TT, 256>>>(ph, pre_attn_w + (long)i * DMODEL, px);

        // qkv: 128x1152x1536, weights [K,N] -> TRANS, splits 6 (Kc=192)
        run_mma(px, DMODEL, 0, w_qkv + (long)i * DMODEL * QKVW, QKVW, 0, true,
                pqkv, QKVW, 0, ppart, QKVW, DMODEL, 6, 1);

        copyk_kernel<<<(CCTX * HDIM + 255) / 256, 256>>>(kv_k + (long)i * CCTX * HDIM);
        copyv_kernel<<<(HDIM * CCTX + 255) / 256, 256>>>(kv_v + (long)i * HDIM * CCTX);

        qkvpost_kernel<<<dim3(TT, 6), HDIM>>>(q_norm_w + (long)i * HDIM,
                                              k_norm_w + (long)i * HDIM, pcos, psin,
                                              out_k + (long)i * TT * HDIM,
                                              out_v + (long)i * HDIM * TT);

        // scores: per-head 128x256x2048, B=kfull [S,HD] K-major, splits 2 (Kc=128)
        run_mma(pq, HDIM, (long)TT * HDIM, pkf, HDIM, 0, false,
                psc, SS, (long)TT * SS, ppart, SS, HDIM, 2, NHD);

        softmax_kernel<<<dim3(TT, NHD), 256>>>(mask);

        // attn@V: per-head 128x2048x256, B=vfull [HD,S] K-major, splits 16 (Kc=128)
        run_mma(psc, SS, (long)TT * SS, pvf, SS, 0, false,
                pao, NHD * HDIM, (long)HDIM, ppart, HDIM, SS, 16, NHD);

        // proj: 128x1024x1152, TRANS, splits 8 (Kc=128)
        run_mma(pao, NHD * HDIM, 0, w_out + (long)i * NHD * HDIM * DMODEL, DMODEL, 0, true,
                ppr, DMODEL, 0, ppart, DMODEL, NHD * HDIM, 8, 1);

        addrms_kernel<<<TT, 256>>>(ppr, post_attn_w + (long)i * DMODEL);
        rmsnorm_kernel<<<TT, 256>>>(ph, pre_ff_w + (long)i * DMODEL, px);

        // gate/up: 128x1152x6912, TRANS, splits 2 (Kc=576)
        run_mma(px, DMODEL, 0, w_gate + (long)i * DMODEL * FDIM, FDIM, 0, true,
                pfa, FDIM, 0, ppart, FDIM, DMODEL, 2, 1);
        run_mma(px, DMODEL, 0, w_up + (long)i * DMODEL * FDIM, FDIM, 0, true,
                pfb, FDIM, 0, ppart, FDIM, DMODEL, 2, 1);

        gelumul_kernel<<<(TT * FDIM + 255) / 256, 256>>>();

        // down: 128x6912x1152, TRANS, splits 12 (Kc=576)
        run_mma(pfa, FDIM, 0, w_down + (long)i * FDIM * DMODEL, DMODEL, 0, true,
                ppr, DMODEL, 0, ppart, DMODEL, FDIM, 12, 1);

        addrms_kernel<<<TT, 256>>>(ppr, post_ff_w + (long)i * DMODEL);
    }

    rmsnorm_kernel<<<TT, 256>>>(ph, final_w, px);
    // lm: 128x1152x32768, TRANS, no split (256 CTAs)
    run_mma(px, DMODEL, 0, w_lm, VOC, 0, true,
            out_logits, VOC, 0, ppart, VOC, DMODEL, 1, 1);
}